// round 5
// baseline (speedup 1.0000x reference)
#include <cuda_runtime.h>

#define Hh 32
#define Bb 64
#define Tt 16384
#define CHUNK 32
#define NCHUNK (Tt / CHUNK)
#define S1 2.8853900817779268f   /* 2*log2(e) */

__device__ __forceinline__ unsigned long long pk2(float lo, float hi) {
    unsigned long long d; asm("mov.b64 %0,{%1,%2};" : "=l"(d) : "f"(lo), "f"(hi)); return d;
}
__device__ __forceinline__ void upk2(unsigned long long v, float& lo, float& hi) {
    asm("mov.b64 {%0,%1},%2;" : "=f"(lo), "=f"(hi) : "l"(v));
}
__device__ __forceinline__ unsigned long long ffma2(unsigned long long a, unsigned long long b, unsigned long long c) {
    unsigned long long d; asm("fma.rn.f32x2 %0,%1,%2,%3;" : "=l"(d) : "l"(a), "l"(b), "l"(c)); return d;
}
__device__ __forceinline__ unsigned long long fadd2(unsigned long long a, unsigned long long b) {
    unsigned long long d; asm("add.rn.f32x2 %0,%1,%2;" : "=l"(d) : "l"(a), "l"(b)); return d;
}
__device__ __forceinline__ float red2(unsigned long long a0, unsigned long long a1,
                                      unsigned long long a2, unsigned long long a3) {
    unsigned long long s = fadd2(fadd2(a0, a1), fadd2(a2, a3));
    float lo, hi; upk2(s, lo, hi);
    return lo + hi;
}

// r = 1/(exp2(arg)+1), arg pre-scaled by 2*log2(e)
__device__ __forceinline__ float sigm_neg(float arg) {
    float e; asm("ex2.approx.f32 %0,%1;" : "=f"(e) : "f"(arg));
    float r; asm("rcp.approx.f32 %0,%1;" : "=f"(r) : "f"(e + 1.0f));
    return r;
}

#define LOADP(a) \
    unsigned long long p0,p1,p2,p3,p4,p5,p6,p7,p8,p9,pa,pb,pc,pd,pe,pf; \
    asm volatile("ld.shared.v2.u64 {%0,%1},[%2];"    : "=l"(p0), "=l"(p1) : "r"(a)); \
    asm volatile("ld.shared.v2.u64 {%0,%1},[%2+16];" : "=l"(p2), "=l"(p3) : "r"(a)); \
    asm volatile("ld.shared.v2.u64 {%0,%1},[%2+32];" : "=l"(p4), "=l"(p5) : "r"(a)); \
    asm volatile("ld.shared.v2.u64 {%0,%1},[%2+48];" : "=l"(p6), "=l"(p7) : "r"(a)); \
    asm volatile("ld.shared.v2.u64 {%0,%1},[%2+64];" : "=l"(p8), "=l"(p9) : "r"(a)); \
    asm volatile("ld.shared.v2.u64 {%0,%1},[%2+80];" : "=l"(pa), "=l"(pb) : "r"(a)); \
    asm volatile("ld.shared.v2.u64 {%0,%1},[%2+96];" : "=l"(pc), "=l"(pd) : "r"(a)); \
    asm volatile("ld.shared.v2.u64 {%0,%1},[%2+112];": "=l"(pe), "=l"(pf) : "r"(a));

#define DOT16(w2, seed, res) { \
    unsigned long long a0 = pk2(seed, 0.f), a1 = 0ull, a2 = 0ull, a3 = 0ull; \
    a0 = ffma2(w2[0],  p0, a0); a1 = ffma2(w2[1],  p1, a1); \
    a2 = ffma2(w2[2],  p2, a2); a3 = ffma2(w2[3],  p3, a3); \
    a0 = ffma2(w2[4],  p4, a0); a1 = ffma2(w2[5],  p5, a1); \
    a2 = ffma2(w2[6],  p6, a2); a3 = ffma2(w2[7],  p7, a3); \
    a0 = ffma2(w2[8],  p8, a0); a1 = ffma2(w2[9],  p9, a1); \
    a2 = ffma2(w2[10], pa, a2); a3 = ffma2(w2[11], pb, a3); \
    a0 = ffma2(w2[12], pc, a0); a1 = ffma2(w2[13], pd, a1); \
    a2 = ffma2(w2[14], pe, a2); a3 = ffma2(w2[15], pf, a3); \
    res = red2(a0, a1, a2, a3); }

// load packed, pre-scaled (-2*S1) weight rows + plain rowsum
__device__ __forceinline__ float load_w2(const float* __restrict__ W, int lane,
                                         unsigned long long* w2, float m) {
    float rs = 0.f;
    #pragma unroll
    for (int k = 0; k < 16; ++k) {
        float u0 = W[lane * Hh + 2 * k], u1 = W[lane * Hh + 2 * k + 1];
        rs += u0 + u1;
        w2[k] = pk2(m * u0, m * u1);
    }
    return rs;
}

__global__ __launch_bounds__(96, 1) void rnn_pipe_kernel(
    const float* __restrict__ x,        const float* __restrict__ h_state,
    const float* __restrict__ W_ih0,    const float* __restrict__ W_hh0,
    const float* __restrict__ b_ih0,    const float* __restrict__ b_hh0,
    const float* __restrict__ W_ih1,    const float* __restrict__ W_hh1,
    const float* __restrict__ b_ih1,    const float* __restrict__ b_hh1,
    const float* __restrict__ W_out,    const float* __restrict__ b_out,
    float* __restrict__ out)
{
    __shared__ __align__(16) float su [4][CHUNK][Hh];   // A -> B1: u'(t') ring, 4-deep
    __shared__ float sh1[2][CHUNK][Hh + 1];             // B1 -> C  (r1, padded)
    __shared__ __align__(16) float hx0[Hh];             // warp A step exchange
    __shared__ __align__(16) float hx1[Hh];             // warp B1 step exchange

    const int b    = blockIdx.x;
    const int lane = threadIdx.x & 31;
    const int wid  = threadIdx.x >> 5;
    const unsigned FULL = 0xffffffffu;
    const float m = -2.0f * S1;

    if (wid == 0) {
        // ---- Warp A: layer-0 recurrence + layer-1 input projection ----
        unsigned long long w2[16], wu[16];
        float rs0 = load_w2(W_hh0, lane, w2, m);
        float rsu = load_w2(W_ih1, lane, wu, m);
        const float wis   = W_ih0[lane] * S1;
        const float bias0 = S1 * (b_ih0[lane] + b_hh0[lane] + rs0);
        const float useed = S1 * rsu;
        float r = fmaf(-0.5f, h_state[b * Hh + lane], 0.5f);
        unsigned int hx0a = (unsigned int)__cvta_generic_to_shared(hx0);

        const float* xb = x + (size_t)b * Tt;
        float xc = xb[lane];
        for (int g = 0; g < NCHUNK + 3; ++g) {
            if (g < NCHUNK) {
                float xn = (g + 1 < NCHUNK) ? xb[(g + 1) * CHUNK + lane] : 0.f;
                #pragma unroll 4
                for (int s = 0; s < CHUNK; ++s) {
                    float xterm = fmaf(__shfl_sync(FULL, xc, s), wis, bias0); // off-chain
                    asm volatile("st.shared.f32 [%0], %1;" :: "r"(hx0a + lane * 4), "f"(r));
                    LOADP(hx0a);                              // p = h-exchange (r0(t-1))
                    float d;  DOT16(w2, xterm, d);            // recurrent dot (on-chain)
                    float uo; DOT16(wu, useed, uo);           // u(t-1) projection (off-chain)
                    r = sigm_neg(d);
                    int tp   = g * CHUNK + s - 1;             // global index of u
                    int buf  = (tp >> 5) & 3;                 // -1 -> buf 3 slot 31 (dead)
                    int slot = tp & 31;
                    su[buf][slot][lane] = uo;
                }
                xc = xn;
            } else if (g == NCHUNK) {
                // flush u(T-1)
                asm volatile("st.shared.f32 [%0], %1;" :: "r"(hx0a + lane * 4), "f"(r));
                LOADP(hx0a);
                float uo; DOT16(wu, useed, uo);
                int tp = NCHUNK * CHUNK - 1;
                su[(tp >> 5) & 3][tp & 31][lane] = uo;
            }
            __syncthreads();
        }
        out[(size_t)Bb * Tt + b * Hh + lane] = fmaf(-2.f, r, 1.f);   // h_final L0

    } else if (wid == 1) {
        // ---- Warp B1: layer-1 recurrence (lags A by 2 chunks) ----
        unsigned long long w2[16];
        float rs1 = load_w2(W_hh1, lane, w2, m);
        const float bias1 = S1 * (b_ih1[lane] + b_hh1[lane] + rs1);
        float r = fmaf(-0.5f, h_state[Bb * Hh + b * Hh + lane], 0.5f);
        unsigned int hx1a = (unsigned int)__cvta_generic_to_shared(hx1);
        for (int g = 0; g < NCHUNK + 3; ++g) {
            if (g >= 2 && g <= NCHUNK + 1) {
                int c = g - 2;
                int ring = c & 3;
                float (*dst)[Hh + 1] = sh1[c & 1];
                #pragma unroll 4
                for (int s = 0; s < CHUNK; ++s) {
                    float uv = su[ring][s][lane] + bias1;     // off-chain, hoistable
                    asm volatile("st.shared.f32 [%0], %1;" :: "r"(hx1a + lane * 4), "f"(r));
                    LOADP(hx1a);
                    float d; DOT16(w2, uv, d);
                    r = sigm_neg(d);
                    dst[s][lane] = r;
                }
            }
            __syncthreads();
        }
        out[(size_t)Bb * Tt + Bb * Hh + b * Hh + lane] = fmaf(-2.f, r, 1.f);  // h_final L1

    } else {
        // ---- Warp C: outs(t) = (b_out + rowsum) - 2*W_out . r1 (lags A by 3) ----
        float wc[Hh];
        float csum = b_out[0];
        #pragma unroll
        for (int k = 0; k < Hh; ++k) { float w = W_out[k]; csum += w; wc[k] = -2.f * w; }
        float* ob = out + (size_t)b * Tt;
        for (int g = 0; g < NCHUNK + 3; ++g) {
            if (g >= 3) {
                int gg  = g - 3;
                int buf = gg & 1;
                const float* hv = sh1[buf][lane];             // lane = timestep in chunk
                float a0 = 0.f, a1 = 0.f, a2 = 0.f, a3 = 0.f;
                #pragma unroll
                for (int k = 0; k < 8; ++k) {
                    a0 = fmaf(wc[k],      hv[k],      a0);
                    a1 = fmaf(wc[k + 8],  hv[k + 8],  a1);
                    a2 = fmaf(wc[k + 16], hv[k + 16], a2);
                    a3 = fmaf(wc[k + 24], hv[k + 24], a3);
                }
                ob[gg * CHUNK + lane] = (((a0 + a1) + (a2 + a3)) + csum);
            }
            __syncthreads();
        }
    }
}

extern "C" void kernel_launch(void* const* d_in, const int* in_sizes, int n_in,
                              void* d_out, int out_size) {
    (void)in_sizes; (void)n_in; (void)out_size;
    rnn_pipe_kernel<<<Bb, 96>>>(
        (const float*)d_in[0],  (const float*)d_in[1],  (const float*)d_in[2],
        (const float*)d_in[3],  (const float*)d_in[4],  (const float*)d_in[5],
        (const float*)d_in[6],  (const float*)d_in[7],  (const float*)d_in[8],
        (const float*)d_in[9],  (const float*)d_in[10], (const float*)d_in[11],
        (float*)d_out);
}